// round 1
// baseline (speedup 1.0000x reference)
#include <cuda_runtime.h>
#include <cuda_bf16.h>

// BlockAttnRes: per-token (b,t) block attention over N=9 source rows of D=512.
//   rms_n   = sqrt(mean(src_n^2) + 1e-6)
//   score_n = dot(src_n, w) / rms_n           (w = queries[layer_idx])
//   alpha   = softmax(score)                  (over n)
//   h       = sum_n alpha_n * src_n
//
// One CTA per token. 128 threads; each thread owns 4 contiguous floats (float4)
// of each of the 9 rows -> all data register-resident for both passes (single
// DRAM read of sources).

#define NN 9
#define DD 512
#define THREADS 128

__global__ __launch_bounds__(THREADS)
void blockattn_kernel(const float* __restrict__ src,
                      const float* __restrict__ queries,
                      const int*   __restrict__ layer_idx,
                      float*       __restrict__ out)
{
    const int tid  = threadIdx.x;
    const int lane = tid & 31;
    const int warp = tid >> 5;

    const long long token = blockIdx.x;
    const float4* base = reinterpret_cast<const float4*>(src + token * (long long)(NN * DD));

    // Query row (L2-resident, broadcast across all CTAs)
    const int li = *layer_idx;
    const float4 w4 = reinterpret_cast<const float4*>(queries + (long long)li * DD)[tid];

    // ---- Phase 1: load all 9 rows into registers (front-batched, coalesced) ----
    float4 v[NN];
#pragma unroll
    for (int n = 0; n < NN; n++)
        v[n] = base[n * (DD / 4) + tid];

    // ---- Per-thread partials: sum of squares & dot with w, per row ----
    float ss[NN], dt[NN];
#pragma unroll
    for (int n = 0; n < NN; n++) {
        const float4 a = v[n];
        ss[n] = a.x * a.x + a.y * a.y + a.z * a.z + a.w * a.w;
        dt[n] = a.x * w4.x + a.y * w4.y + a.z * w4.z + a.w * w4.w;
    }

    // ---- Warp reduction ----
#pragma unroll
    for (int n = 0; n < NN; n++) {
#pragma unroll
        for (int o = 16; o > 0; o >>= 1) {
            ss[n] += __shfl_xor_sync(0xffffffffu, ss[n], o);
            dt[n] += __shfl_xor_sync(0xffffffffu, dt[n], o);
        }
    }

    // ---- Cross-warp reduction via shared ----
    __shared__ float s_ss[NN][4];
    __shared__ float s_dt[NN][4];
    __shared__ float s_alpha[NN];

    if (lane == 0) {
#pragma unroll
        for (int n = 0; n < NN; n++) {
            s_ss[n][warp] = ss[n];
            s_dt[n][warp] = dt[n];
        }
    }
    __syncthreads();

    if (tid == 0) {
        float sc[NN];
        float mx = -3.4e38f;
#pragma unroll
        for (int n = 0; n < NN; n++) {
            const float S  = s_ss[n][0] + s_ss[n][1] + s_ss[n][2] + s_ss[n][3];
            const float Dt = s_dt[n][0] + s_dt[n][1] + s_dt[n][2] + s_dt[n][3];
            const float rinv = rsqrtf(S * (1.0f / DD) + 1e-6f);
            sc[n] = Dt * rinv;
            mx = fmaxf(mx, sc[n]);
        }
        float sum = 0.0f;
#pragma unroll
        for (int n = 0; n < NN; n++) {
            sc[n] = __expf(sc[n] - mx);
            sum += sc[n];
        }
        const float inv = 1.0f / sum;
#pragma unroll
        for (int n = 0; n < NN; n++)
            s_alpha[n] = sc[n] * inv;
    }
    __syncthreads();

    // ---- Phase 2: weighted sum from register-resident rows ----
    float4 o = make_float4(0.f, 0.f, 0.f, 0.f);
#pragma unroll
    for (int n = 0; n < NN; n++) {
        const float a = s_alpha[n];
        o.x += a * v[n].x;
        o.y += a * v[n].y;
        o.z += a * v[n].z;
        o.w += a * v[n].w;
    }

    reinterpret_cast<float4*>(out + token * (long long)DD)[tid] = o;
}

extern "C" void kernel_launch(void* const* d_in, const int* in_sizes, int n_in,
                              void* d_out, int out_size)
{
    const float* src     = (const float*)d_in[0];
    const float* queries = (const float*)d_in[1];
    const int*   lidx    = (const int*)d_in[2];
    float*       out     = (float*)d_out;

    const int tokens = in_sizes[0] / (NN * DD);   // B*T = 32768
    blockattn_kernel<<<tokens, THREADS>>>(src, queries, lidx, out);
}